// round 11
// baseline (speedup 1.0000x reference)
#include <cuda_runtime.h>
#include <cuda_bf16.h>
#include <cstdint>
#include <math.h>

#define NB 512
#define SEQ 128
#define D 256
#define NREST 65024            // NB*(SEQ-1)

#define BM 128
#define BROWS 127              // real columns per tile = one batch of rest rows
#define GRIDX 4                // NB/BM
#define GRIDY 74               // persistent: 4*74 = 296 CTAs = 2/SM
#define NTILES NB              // 512 tiles, one per batch
#define TOTAL_BLOCKS (GRIDX * GRIDY)

#define SROW 272               // bytes per smem row: 256 s8 + 16 pad (conflict-free LDSM)
#define TILE_BYTES (128 * SROW)   // 34816 (includes zero pad row 127)

// dynamic smem layout (bytes)
#define SM_A 0
#define SM_B TILE_BYTES                       // two stages: + (t&1)*TILE_BYTES
#define SM_MISC (SM_B + 2 * TILE_BYTES)
#define SM_TOTAL (SM_MISC + 2 * BM * 4 + 64 + 64 * 4)

#define INV_SCALE (1.0f / 16129.0f)           // 1/(127*127)

// ---------------- device scratch ----------------
__device__ int8_t g_anchors[NB * D];          // q = round(127 * x)
__device__ int8_t g_rest[(size_t)NREST * D];
__device__ int   g_labels[NB];
__device__ float g_tot[NB];
__device__ float g_pos[NB];
__device__ unsigned g_done;

__device__ __forceinline__ uint32_t smem_u32(const void* p) {
    return (uint32_t)__cvta_generic_to_shared(p);
}
__device__ __forceinline__ void cp_async16(uint32_t dst, const void* src) {
    asm volatile("cp.async.cg.shared.global [%0], [%1], 16;" :: "r"(dst), "l"(src) : "memory");
}
__device__ __forceinline__ void cp_commit() {
    asm volatile("cp.async.commit_group;" ::: "memory");
}
template <int N>
__device__ __forceinline__ void cp_wait() {
    asm volatile("cp.async.wait_group %0;" :: "n"(N) : "memory");
}
__device__ __forceinline__ uint32_t pack_s8x4(float x0, float x1, float x2, float x3) {
    int i0 = __float2int_rn(x0), i1 = __float2int_rn(x1);
    int i2 = __float2int_rn(x2), i3 = __float2int_rn(x3);
    uint32_t r;
    asm("{ .reg .u32 t0, t1;\n\t"
        "cvt.pack.sat.s8.s32.b32 t0, %2, %1, 0;\n\t"
        "cvt.pack.sat.s8.s32.b32 %0, %4, %3, t0;\n\t}"
        : "=r"(r) : "r"(i0), "r"(i1), "r"(i2), "r"(i3));
    return r;
}

// ---------------- kernel 1: normalize + init, write s8 ----------------
__global__ void normalize_kernel(const float* __restrict__ inp, const int* __restrict__ lab) {
    int gtid = blockIdx.x * 256 + threadIdx.x;
    if (gtid < NB) { g_tot[gtid] = 0.0f; g_pos[gtid] = 0.0f; g_labels[gtid] = lab[gtid]; }
    if (gtid == 0) g_done = 0u;

    int row  = blockIdx.x * 8 + (threadIdx.x >> 5);
    int lane = threadIdx.x & 31;
    const float4* p = reinterpret_cast<const float4*>(inp + (size_t)row * D) + lane * 2;
    float4 a = p[0];
    float4 b = p[1];
    float ss = a.x*a.x + a.y*a.y + a.z*a.z + a.w*a.w
             + b.x*b.x + b.y*b.y + b.z*b.z + b.w*b.w;
    #pragma unroll
    for (int o = 16; o > 0; o >>= 1) ss += __shfl_xor_sync(0xffffffffu, ss, o);
    float scale = 127.0f / fmaxf(sqrtf(ss), 1e-12f);

    int bidx = row >> 7;
    int l    = row & 127;
    int8_t* dst = (l == 0)
        ? (g_anchors + (size_t)bidx * D)
        : (g_rest + (size_t)(bidx * (SEQ - 1) + (l - 1)) * D);

    uint2 u;
    u.x = pack_s8x4(a.x * scale, a.y * scale, a.z * scale, a.w * scale);
    u.y = pack_s8x4(b.x * scale, b.y * scale, b.z * scale, b.w * scale);
    *reinterpret_cast<uint2*>(dst + lane * 8) = u;
}

// ---------------- kernel 2: persistent INT8 GEMM, batch-aligned tiles ----------------
__global__ void __launch_bounds__(256, 2) score_kernel(float* __restrict__ out) {
    extern __shared__ __align__(16) char S[];

    float* sTot  = reinterpret_cast<float*>(S + SM_MISC);
    float* sPos  = sTot + BM;
    int*   sFlag = reinterpret_cast<int*>(sPos + BM);
    int*   sHist = sFlag + 16;

    int tid  = threadIdx.x;
    int lane = tid & 31;
    int warp = tid >> 5;
    int wm = (warp & 3) * 32;   // 4 warps along M
    int wn = (warp >> 2) * 64;  // 2 warps along N
    int bm = blockIdx.x * BM;
    int gy = blockIdx.y;
    int T  = (NTILES - gy + GRIDY - 1) / GRIDY;   // 7 or 6 tiles (batches)

    if (tid < BM) { sTot[tid] = 0.0f; sPos[tid] = 0.0f; }

    const int8_t* gA = g_anchors + (size_t)bm * D;
    uint32_t smA = smem_u32(S + SM_A);
    uint32_t smB = smem_u32(S + SM_B);

    // zero the pad row (row 127) of both B stages once; never overwritten
    if (tid < 32) {
        int st = tid >> 4, c = tid & 15;
        *reinterpret_cast<uint4*>(S + SM_B + st * TILE_BYTES + 127 * SROW + c * 16) =
            make_uint4(0u, 0u, 0u, 0u);
    }

    // B tile load: 127 rows x 256B = 2032 16B-chunks
    #define ISSUE_B(t_, st_)                                                        \
        do {                                                                        \
            int _j = gy + (t_) * GRIDY;                                             \
            const int8_t* _gB = g_rest + (size_t)_j * BROWS * D;                    \
            _Pragma("unroll")                                                       \
            for (int i = 0; i < 8; i++) {                                           \
                int idx = tid + i * 256;                                            \
                if (idx < BROWS * 16) {                                             \
                    int r = idx >> 4, c = idx & 15;                                 \
                    cp_async16(smB + (st_) * TILE_BYTES + r * SROW + c * 16,        \
                               _gB + (size_t)r * D + c * 16);                       \
                }                                                                   \
            }                                                                       \
            cp_commit();                                                            \
        } while (0)

    // prologue: A + B0 in group 0; B1 in group 1
    #pragma unroll
    for (int i = 0; i < 8; i++) {
        int idx = tid + i * 256;
        int r = idx >> 4, c = idx & 15;
        cp_async16(smA + r * SROW + c * 16, gA + (size_t)r * D + c * 16);
    }
    ISSUE_B(0, 0);        // commits group 0 (A + B0)
    ISSUE_B(1, 1);        // group 1

    // row labels fixed per thread for the whole kernel
    int qr = lane >> 2;
    int rlab[2][2];
    #pragma unroll
    for (int mf = 0; mf < 2; mf++)
        #pragma unroll
        for (int h = 0; h < 2; h++)
            rlab[mf][h] = g_labels[bm + wm + mf * 16 + h * 8 + qr];

    float rts[2][2] = {{0.f, 0.f}, {0.f, 0.f}};
    float rps[2][2] = {{0.f, 0.f}, {0.f, 0.f}};

    uint32_t afr[2][4], bfr[8][2];

    for (int t = 0; t < T; t++) {
        int j = gy + t * GRIDY;
        int jlab = g_labels[j];          // one label for the whole tile

        if (t + 1 < T) cp_wait<1>(); else cp_wait<0>();
        __syncthreads();

        uint32_t bBase = smB + (t & 1) * TILE_BYTES;

        int acc[2][8][4];
        #pragma unroll
        for (int mf = 0; mf < 2; mf++)
            #pragma unroll
            for (int nf = 0; nf < 8; nf++)
                #pragma unroll
                for (int r = 0; r < 4; r++) acc[mf][nf][r] = 0;

        #pragma unroll
        for (int ks = 0; ks < 8; ks++) {
            #pragma unroll
            for (int mf = 0; mf < 2; mf++) {
                uint32_t addr = smA + (wm + mf * 16 + (lane & 15)) * SROW
                                    + ks * 32 + (lane >> 4) * 16;
                asm volatile("ldmatrix.sync.aligned.m8n8.x4.shared.b16 {%0,%1,%2,%3}, [%4];"
                             : "=r"(afr[mf][0]), "=r"(afr[mf][1]),
                               "=r"(afr[mf][2]), "=r"(afr[mf][3])
                             : "r"(addr));
            }
            #pragma unroll
            for (int np = 0; np < 4; np++) {
                uint32_t addr = bBase + (wn + np * 16 + (lane >> 4) * 8 + (lane & 7)) * SROW
                                      + ks * 32 + ((lane >> 3) & 1) * 16;
                asm volatile("ldmatrix.sync.aligned.m8n8.x4.shared.b16 {%0,%1,%2,%3}, [%4];"
                             : "=r"(bfr[2 * np][0]), "=r"(bfr[2 * np][1]),
                               "=r"(bfr[2 * np + 1][0]), "=r"(bfr[2 * np + 1][1])
                             : "r"(addr));
            }
            #pragma unroll
            for (int mf = 0; mf < 2; mf++)
                #pragma unroll
                for (int nf = 0; nf < 8; nf++)
                    asm volatile(
                        "mma.sync.aligned.m16n8k32.row.col.s32.s8.s8.s32 "
                        "{%0,%1,%2,%3}, {%4,%5,%6,%7}, {%8,%9}, {%0,%1,%2,%3};"
                        : "+r"(acc[mf][nf][0]), "+r"(acc[mf][nf][1]),
                          "+r"(acc[mf][nf][2]), "+r"(acc[mf][nf][3])
                        : "r"(afr[mf][0]), "r"(afr[mf][1]), "r"(afr[mf][2]), "r"(afr[mf][3]),
                          "r"(bfr[nf][0]), "r"(bfr[nf][1]));
        }

        // epilogue: i2f + exp + row sum; single label compare per (row,tile)
        #pragma unroll
        for (int mf = 0; mf < 2; mf++) {
            #pragma unroll
            for (int h = 0; h < 2; h++) {
                float ts = 0.0f;
                #pragma unroll
                for (int nf = 0; nf < 8; nf++) {
                    ts += __expf((float)acc[mf][nf][h * 2 + 0] * INV_SCALE);
                    ts += __expf((float)acc[mf][nf][h * 2 + 1] * INV_SCALE);
                }
                ts += __shfl_xor_sync(0xffffffffu, ts, 1);
                ts += __shfl_xor_sync(0xffffffffu, ts, 2);
                if ((lane & 3) == 0) {
                    rts[mf][h] += ts;
                    rps[mf][h] += (jlab == rlab[mf][h]) ? ts : 0.0f;
                }
            }
        }

        // stage (t&1) fully consumed -> refill
        __syncthreads();
        if (t + 2 < T) ISSUE_B(t + 2, t & 1);
    }

    // drain per-thread accumulators -> smem -> global
    if ((lane & 3) == 0) {
        #pragma unroll
        for (int mf = 0; mf < 2; mf++)
            #pragma unroll
            for (int h = 0; h < 2; h++) {
                int lrow = wm + mf * 16 + h * 8 + qr;
                atomicAdd(&sTot[lrow], rts[mf][h]);
                atomicAdd(&sPos[lrow], rps[mf][h]);
            }
    }
    __syncthreads();
    if (tid < BM) {
        atomicAdd(&g_tot[bm + tid], sTot[tid]);
        atomicAdd(&g_pos[bm + tid], sPos[tid]);
    }

    // ---- fused finalize: last CTA computes the loss ----
    __threadfence();
    __syncthreads();
    if (tid == 0) {
        unsigned v = atomicAdd(&g_done, 1u);
        sFlag[0] = (v == TOTAL_BLOCKS - 1) ? 1 : 0;
    }
    __syncthreads();
    if (sFlag[0]) {
        __threadfence();
        // histogram of labels (pad-column correction for pos)
        if (tid < 64) sHist[tid] = 0;
        __syncthreads();
        int l0 = g_labels[tid], l1 = g_labels[tid + 256];
        atomicAdd(&sHist[l0], 1);
        atomicAdd(&sHist[l1], 1);
        __syncthreads();
        // every tile adds exp(0)=1 to tot; same-label tiles add 1 to pos
        float v = (logf(g_tot[tid]       - 512.0f) - logf(g_pos[tid]       - (float)sHist[l0]))
                + (logf(g_tot[tid + 256] - 512.0f) - logf(g_pos[tid + 256] - (float)sHist[l1]));
        #pragma unroll
        for (int o = 16; o > 0; o >>= 1) v += __shfl_xor_sync(0xffffffffu, v, o);
        float* red = sTot;   // reuse
        if (lane == 0) red[warp] = v;
        __syncthreads();
        if (tid == 0) {
            float s = 0.0f;
            #pragma unroll
            for (int w = 0; w < 8; w++) s += red[w];
            out[0] = s * (1.0f / 512.0f);
        }
    }
}

// ---------------- launch ----------------
extern "C" void kernel_launch(void* const* d_in, const int* in_sizes, int n_in,
                              void* d_out, int out_size) {
    const float* inp = (const float*)d_in[0];
    const int*   lab = (const int*)d_in[1];
    float*       out = (float*)d_out;

    cudaFuncSetAttribute(score_kernel, cudaFuncAttributeMaxDynamicSharedMemorySize, SM_TOTAL);

    normalize_kernel<<<(NB * SEQ) / 8, 256>>>(inp, lab);
    score_kernel<<<dim3(GRIDX, GRIDY), 256, SM_TOTAL>>>(out);
}

// round 12
// speedup vs baseline: 2.0335x; 2.0335x over previous
#include <cuda_runtime.h>
#include <cuda_bf16.h>
#include <cuda_fp16.h>
#include <cuda_fp8.h>
#include <cstdint>
#include <math.h>

#define NB 512
#define SEQ 128
#define D 256
#define NREST 65024            // NB*(SEQ-1)

#define BM 128
#define BROWS 127              // real columns per tile = one batch of rest rows
#define GRIDX 4                // NB/BM
#define GRIDY 74               // persistent: 4*74 = 296 CTAs = 2/SM
#define NTILES NB              // 512 tiles, one per batch
#define TOTAL_BLOCKS (GRIDX * GRIDY)

#define SROW 272               // bytes per smem row: 256 fp8 + 16 pad (conflict-free LDSM)
#define TILE_BYTES (128 * SROW)   // 34816 (includes zero pad row 127)

// dynamic smem layout (bytes)
#define SM_A 0
#define SM_B TILE_BYTES                       // two stages: + (t&1)*TILE_BYTES
#define SM_MISC (SM_B + 2 * TILE_BYTES)
#define SM_TOTAL (SM_MISC + 2 * BM * 4 + 64 + 64 * 4)

// ---------------- device scratch ----------------
__device__ uint8_t g_anchors[NB * D];        // e4m3
__device__ uint8_t g_rest[(size_t)NREST * D];
__device__ int   g_labels[NB];
__device__ float g_tot[NB];
__device__ float g_pos[NB];
__device__ unsigned g_done;

__device__ __forceinline__ uint32_t smem_u32(const void* p) {
    return (uint32_t)__cvta_generic_to_shared(p);
}
__device__ __forceinline__ void cp_async16(uint32_t dst, const void* src) {
    asm volatile("cp.async.cg.shared.global [%0], [%1], 16;" :: "r"(dst), "l"(src) : "memory");
}
__device__ __forceinline__ void cp_commit() {
    asm volatile("cp.async.commit_group;" ::: "memory");
}
template <int N>
__device__ __forceinline__ void cp_wait() {
    asm volatile("cp.async.wait_group %0;" :: "n"(N) : "memory");
}

// ---------------- kernel 1: normalize + init, write e4m3 ----------------
__global__ void normalize_kernel(const float* __restrict__ inp, const int* __restrict__ lab) {
    int gtid = blockIdx.x * 256 + threadIdx.x;
    if (gtid < NB) { g_tot[gtid] = 0.0f; g_pos[gtid] = 0.0f; g_labels[gtid] = lab[gtid]; }
    if (gtid == 0) g_done = 0u;

    int row  = blockIdx.x * 8 + (threadIdx.x >> 5);
    int lane = threadIdx.x & 31;
    const float4* p = reinterpret_cast<const float4*>(inp + (size_t)row * D) + lane * 2;
    float4 a = p[0];
    float4 b = p[1];
    float ss = a.x*a.x + a.y*a.y + a.z*a.z + a.w*a.w
             + b.x*b.x + b.y*b.y + b.z*b.z + b.w*b.w;
    #pragma unroll
    for (int o = 16; o > 0; o >>= 1) ss += __shfl_xor_sync(0xffffffffu, ss, o);
    float scale = 1.0f / fmaxf(sqrtf(ss), 1e-12f);

    int bidx = row >> 7;
    int l    = row & 127;
    uint8_t* dst = (l == 0)
        ? (g_anchors + (size_t)bidx * D)
        : (g_rest + (size_t)(bidx * (SEQ - 1) + (l - 1)) * D);

    __nv_fp8x2_storage_t q0 = __nv_cvt_float2_to_fp8x2(
        make_float2(a.x * scale, a.y * scale), __NV_SATFINITE, __NV_E4M3);
    __nv_fp8x2_storage_t q1 = __nv_cvt_float2_to_fp8x2(
        make_float2(a.z * scale, a.w * scale), __NV_SATFINITE, __NV_E4M3);
    __nv_fp8x2_storage_t q2 = __nv_cvt_float2_to_fp8x2(
        make_float2(b.x * scale, b.y * scale), __NV_SATFINITE, __NV_E4M3);
    __nv_fp8x2_storage_t q3 = __nv_cvt_float2_to_fp8x2(
        make_float2(b.z * scale, b.w * scale), __NV_SATFINITE, __NV_E4M3);
    uint2 u;
    u.x = (uint32_t)q0 | ((uint32_t)q1 << 16);
    u.y = (uint32_t)q2 | ((uint32_t)q3 << 16);
    *reinterpret_cast<uint2*>(dst + lane * 8) = u;
}

// ---------------- kernel 2: persistent FP8 GEMM, batch-aligned tiles ----------------
__global__ void __launch_bounds__(256, 2) score_kernel(float* __restrict__ out) {
    extern __shared__ __align__(16) char S[];

    float* sTot  = reinterpret_cast<float*>(S + SM_MISC);
    float* sPos  = sTot + BM;
    int*   sFlag = reinterpret_cast<int*>(sPos + BM);
    int*   sHist = sFlag + 16;

    int tid  = threadIdx.x;
    int lane = tid & 31;
    int warp = tid >> 5;
    int wm = (warp & 3) * 32;   // 4 warps along M
    int wn = (warp >> 2) * 64;  // 2 warps along N
    int bm = blockIdx.x * BM;
    int gy = blockIdx.y;
    int bid = blockIdx.x + blockIdx.y * GRIDX;
    int T  = (NTILES - gy + GRIDY - 1) / GRIDY;   // 7 or 6 tiles (batches)

    if (tid < BM) { sTot[tid] = 0.0f; sPos[tid] = 0.0f; }

    const uint8_t* gA = g_anchors + (size_t)bm * D;
    uint32_t smA = smem_u32(S + SM_A);
    uint32_t smB = smem_u32(S + SM_B);

    // zero the pad row (row 127) of both B stages once; never overwritten
    if (tid < 32) {
        int st = tid >> 4, c = tid & 15;
        *reinterpret_cast<uint4*>(S + SM_B + st * TILE_BYTES + 127 * SROW + c * 16) =
            make_uint4(0u, 0u, 0u, 0u);
    }

    // B tile load: 127 rows x 256B = 2032 16B-chunks
    #define ISSUE_B(t_, st_)                                                        \
        do {                                                                        \
            int _j = gy + (t_) * GRIDY;                                             \
            const uint8_t* _gB = g_rest + (size_t)_j * BROWS * D;                   \
            _Pragma("unroll")                                                       \
            for (int i = 0; i < 8; i++) {                                           \
                int idx = tid + i * 256;                                            \
                if (idx < BROWS * 16) {                                             \
                    int r = idx >> 4, c = idx & 15;                                 \
                    cp_async16(smB + (st_) * TILE_BYTES + r * SROW + c * 16,        \
                               _gB + (size_t)r * D + c * 16);                       \
                }                                                                   \
            }                                                                       \
            cp_commit();                                                            \
        } while (0)

    // prologue: A + B0 in group 0; B1 in group 1
    #pragma unroll
    for (int i = 0; i < 8; i++) {
        int idx = tid + i * 256;
        int r = idx >> 4, c = idx & 15;
        cp_async16(smA + r * SROW + c * 16, gA + (size_t)r * D + c * 16);
    }
    ISSUE_B(0, 0);        // commits group 0 (A + B0)
    ISSUE_B(1, 1);        // group 1

    // anti-phase stagger: second-wave CTAs (co-resident with a first-wave CTA)
    // delay ~half a tile period so their epilogue overlaps the peer's MMA phase
    if (bid >= 148) {
        long long t0 = clock64();
        while (clock64() - t0 < 3500) { }
    }

    // row labels fixed per thread for the whole kernel
    int qr = lane >> 2;
    int rlab[2][2];
    #pragma unroll
    for (int mf = 0; mf < 2; mf++)
        #pragma unroll
        for (int h = 0; h < 2; h++)
            rlab[mf][h] = g_labels[bm + wm + mf * 16 + h * 8 + qr];

    float rts[2][2] = {{0.f, 0.f}, {0.f, 0.f}};
    float rps[2][2] = {{0.f, 0.f}, {0.f, 0.f}};

    uint32_t afr[2][4], bfr[8][2];
    const float C = 1.4426950408889634f;   // log2(e)

    for (int t = 0; t < T; t++) {
        int j = gy + t * GRIDY;
        int jlab = g_labels[j];          // one label for the whole tile

        if (t + 1 < T) cp_wait<1>(); else cp_wait<0>();
        __syncthreads();

        uint32_t bBase = smB + (t & 1) * TILE_BYTES;

        float acc[2][8][4];
        #pragma unroll
        for (int mf = 0; mf < 2; mf++)
            #pragma unroll
            for (int nf = 0; nf < 8; nf++)
                #pragma unroll
                for (int r = 0; r < 4; r++) acc[mf][nf][r] = 0.0f;

        #pragma unroll
        for (int ks = 0; ks < 8; ks++) {
            #pragma unroll
            for (int mf = 0; mf < 2; mf++) {
                uint32_t addr = smA + (wm + mf * 16 + (lane & 15)) * SROW
                                    + ks * 32 + (lane >> 4) * 16;
                asm volatile("ldmatrix.sync.aligned.m8n8.x4.shared.b16 {%0,%1,%2,%3}, [%4];"
                             : "=r"(afr[mf][0]), "=r"(afr[mf][1]),
                               "=r"(afr[mf][2]), "=r"(afr[mf][3])
                             : "r"(addr));
            }
            #pragma unroll
            for (int np = 0; np < 4; np++) {
                uint32_t addr = bBase + (wn + np * 16 + (lane >> 4) * 8 + (lane & 7)) * SROW
                                      + ks * 32 + ((lane >> 3) & 1) * 16;
                asm volatile("ldmatrix.sync.aligned.m8n8.x4.shared.b16 {%0,%1,%2,%3}, [%4];"
                             : "=r"(bfr[2 * np][0]), "=r"(bfr[2 * np][1]),
                               "=r"(bfr[2 * np + 1][0]), "=r"(bfr[2 * np + 1][1])
                             : "r"(addr));
            }
            #pragma unroll
            for (int mf = 0; mf < 2; mf++)
                #pragma unroll
                for (int nf = 0; nf < 8; nf++)
                    asm volatile(
                        "mma.sync.aligned.m16n8k32.row.col.f32.e4m3.e4m3.f32 "
                        "{%0,%1,%2,%3}, {%4,%5,%6,%7}, {%8,%9}, {%0,%1,%2,%3};"
                        : "+f"(acc[mf][nf][0]), "+f"(acc[mf][nf][1]),
                          "+f"(acc[mf][nf][2]), "+f"(acc[mf][nf][3])
                        : "r"(afr[mf][0]), "r"(afr[mf][1]), "r"(afr[mf][2]), "r"(afr[mf][3]),
                          "r"(bfr[nf][0]), "r"(bfr[nf][1]));
        }

        // epilogue: packed f16x2 exp2 + pair-sum; no shfl (per-thread column share)
        #pragma unroll
        for (int mf = 0; mf < 2; mf++) {
            #pragma unroll
            for (int h = 0; h < 2; h++) {
                __half2 hs = __floats2half2_rn(0.0f, 0.0f);
                #pragma unroll
                for (int nf = 0; nf < 8; nf++) {
                    __half2 hx = __floats2half2_rn(acc[mf][nf][h * 2 + 0] * C,
                                                   acc[mf][nf][h * 2 + 1] * C);
                    hs = __hadd2(hs, h2exp2(hx));
                }
                float2 f = __half22float2(hs);
                float ts = f.x + f.y;
                rts[mf][h] += ts;
                rps[mf][h] += (jlab == rlab[mf][h]) ? ts : 0.0f;
            }
        }

        // stage (t&1) fully consumed -> refill
        __syncthreads();
        if (t + 2 < T) ISSUE_B(t + 2, t & 1);
    }

    // drain: one quad reduction at the end, then smem/global atomics
    #pragma unroll
    for (int mf = 0; mf < 2; mf++) {
        #pragma unroll
        for (int h = 0; h < 2; h++) {
            float ts = rts[mf][h], ps = rps[mf][h];
            ts += __shfl_xor_sync(0xffffffffu, ts, 1);
            ts += __shfl_xor_sync(0xffffffffu, ts, 2);
            ps += __shfl_xor_sync(0xffffffffu, ps, 1);
            ps += __shfl_xor_sync(0xffffffffu, ps, 2);
            if ((lane & 3) == 0) {
                int lrow = wm + mf * 16 + h * 8 + qr;
                atomicAdd(&sTot[lrow], ts);
                atomicAdd(&sPos[lrow], ps);
            }
        }
    }
    __syncthreads();
    if (tid < BM) {
        atomicAdd(&g_tot[bm + tid], sTot[tid]);
        atomicAdd(&g_pos[bm + tid], sPos[tid]);
    }

    // ---- fused finalize: last CTA computes the loss ----
    __threadfence();
    __syncthreads();
    if (tid == 0) {
        unsigned v = atomicAdd(&g_done, 1u);
        sFlag[0] = (v == TOTAL_BLOCKS - 1) ? 1 : 0;
    }
    __syncthreads();
    if (sFlag[0]) {
        __threadfence();
        // histogram of labels (pad-column correction for pos)
        if (tid < 64) sHist[tid] = 0;
        __syncthreads();
        int l0 = g_labels[tid], l1 = g_labels[tid + 256];
        atomicAdd(&sHist[l0], 1);
        atomicAdd(&sHist[l1], 1);
        __syncthreads();
        // every tile adds exp(0)=1 to tot; same-label tiles add 1 to pos
        float v = (logf(g_tot[tid]       - 512.0f) - logf(g_pos[tid]       - (float)sHist[l0]))
                + (logf(g_tot[tid + 256] - 512.0f) - logf(g_pos[tid + 256] - (float)sHist[l1]));
        #pragma unroll
        for (int o = 16; o > 0; o >>= 1) v += __shfl_xor_sync(0xffffffffu, v, o);
        float* red = sTot;   // reuse
        if (lane == 0) red[warp] = v;
        __syncthreads();
        if (tid == 0) {
            float s = 0.0f;
            #pragma unroll
            for (int w = 0; w < 8; w++) s += red[w];
            out[0] = s * (1.0f / 512.0f);
        }
    }
}

// ---------------- launch ----------------
extern "C" void kernel_launch(void* const* d_in, const int* in_sizes, int n_in,
                              void* d_out, int out_size) {
    const float* inp = (const float*)d_in[0];
    const int*   lab = (const int*)d_in[1];
    float*       out = (float*)d_out;

    cudaFuncSetAttribute(score_kernel, cudaFuncAttributeMaxDynamicSharedMemorySize, SM_TOTAL);

    normalize_kernel<<<(NB * SEQ) / 8, 256>>>(inp, lab);
    score_kernel<<<dim3(GRIDX, GRIDY), 256, SM_TOTAL>>>(out);
}